// round 16
// baseline (speedup 1.0000x reference)
#include <cuda_runtime.h>
#include <cuda_fp16.h>
#include <math.h>

#define B_  2
#define C_  64
#define H2_ 256
#define W2_ 256
#define HW2_ (H2_*W2_)
#define H1_ 128
#define W1_ 128
#define HW1_ (H1_*W1_)
#define KK_ 9

typedef unsigned long long u64t;
typedef unsigned int u32t;

__device__ __forceinline__ void mma_f16(float* d, u32t a0, u32t a1, u32t a2, u32t a3,
                                        u32t b0, u32t b1) {
    asm("mma.sync.aligned.m16n8k16.row.col.f32.f16.f16.f32 "
        "{%0,%1,%2,%3},{%4,%5,%6,%7},{%8,%9},{%0,%1,%2,%3};"
        : "+f"(d[0]), "+f"(d[1]), "+f"(d[2]), "+f"(d[3])
        : "r"(a0), "r"(a1), "r"(a2), "r"(a3), "r"(b0), "r"(b1));
}
__device__ __forceinline__ u32t packh2(float lo, float hi) {
    __half2 h = __floats2half2_rn(lo, hi);
    return *(u32t*)&h;
}

// ---------------- scratch ----------------
__device__ float g_wmap[B_*HW2_];
__device__ float g_fuse[B_*KK_*HW2_];
__device__ float g_r2[B_*C_*HW1_];
__device__ float g_r3[B_*C_*HW1_];

// fp16 pair-interleaved buffers: [b][chunk16][px][8 words]
__device__ u32t gt_in0[B_*8*HW2_*8];
__device__ u32t gt_wm1[B_*4*HW2_*8];
__device__ u32t gt_wm2[B_*4*HW2_*8];
__device__ u32t gt_inlo[B_*4*HW1_*8];
__device__ u32t gt_r1[B_*4*HW1_*8];
__device__ u32t gt_r2[B_*4*HW1_*8];
__device__ u32t gt_r3[B_*4*HW1_*8];
// fp16 weights: [chunk16][tap][oc][8 words]
__device__ u32t gt_wn1[8*9*64*8];
__device__ u32t gt_wn2[4*9*64*8];
__device__ u32t gt_rb [4*4*9*64*8];
__device__ u32t gt_wn3[4*9*8*8];
// fp16 fuse weights
__device__ u32t gt_fw1[2*4*64*8];
__device__ u32t gt_fw2[2*4*16*8];

// ---------------------------------------------------------------------------
// merged prep: inputs + all weights -> fp16 pair-interleaved
// ---------------------------------------------------------------------------
#define NPI_ (B_*8*HW2_ + B_*4*HW1_)

__device__ __forceinline__ void wcvt(const float* __restrict__ w, u32t* __restrict__ o,
                                     int widx, int CIN) {
    int ws  = widx & 7;
    int oc  = (widx >> 3) & 63;
    int rem = widx >> 9;
    int tap = rem % 9, chunk = rem / 9;
    int p   = (ws >> 1) + ((ws & 1) << 2);
    int c0  = chunk * 16 + 2 * p;
    o[widx] = packh2(w[(oc * CIN + c0) * 9 + tap], w[(oc * CIN + c0 + 1) * 9 + tap]);
}

__global__ void k_prep(const float* __restrict__ depth, const float* __restrict__ guide,
                       const float* __restrict__ inputs,
                       const float* __restrict__ wn1, const float* __restrict__ wn2,
                       const float* __restrict__ rb,  const float* __restrict__ wn3,
                       const float* __restrict__ dkw1, const float* __restrict__ gkw1,
                       const float* __restrict__ dkw2, const float* __restrict__ gkw2) {
    int idx = blockIdx.x * 256 + threadIdx.x;
    const int N0 = B_ * 8 * HW2_;
    if (idx < N0) {
        int px = idx & (HW2_ - 1);
        int ch = (idx >> 16) & 7;
        int b  = idx >> 19;
        const float* src = (ch < 4 ? depth : guide) + ((size_t)b * 64 + (ch & 3) * 16) * HW2_ + px;
        u32t w[8];
#pragma unroll
        for (int ws = 0; ws < 8; ws++) {
            int p = (ws >> 1) + ((ws & 1) << 2);
            w[ws] = packh2(src[(size_t)(2 * p) * HW2_], src[(size_t)(2 * p + 1) * HW2_]);
        }
        *(uint4*)&gt_in0[(size_t)idx * 8]     = make_uint4(w[0], w[1], w[2], w[3]);
        *(uint4*)&gt_in0[(size_t)idx * 8 + 4] = make_uint4(w[4], w[5], w[6], w[7]);
    } else if (idx < NPI_) {
        int j = idx - N0;
        int px = j & (HW1_ - 1);
        int ch = (j >> 14) & 3;
        int b  = j >> 16;
        const float* src = inputs + ((size_t)b * 64 + ch * 16) * HW1_ + px;
        u32t w[8];
#pragma unroll
        for (int ws = 0; ws < 8; ws++) {
            int p = (ws >> 1) + ((ws & 1) << 2);
            w[ws] = packh2(src[(size_t)(2 * p) * HW1_], src[(size_t)(2 * p + 1) * HW1_]);
        }
        *(uint4*)&gt_inlo[(size_t)j * 8]     = make_uint4(w[0], w[1], w[2], w[3]);
        *(uint4*)&gt_inlo[(size_t)j * 8 + 4] = make_uint4(w[4], w[5], w[6], w[7]);
    } else {
        int widx = idx - NPI_;
        if (widx < 36864) {
            wcvt(wn1, gt_wn1, widx, 128);
        } else if (widx < 55296) {
            wcvt(wn2, gt_wn2, widx - 36864, 64);
        } else if (widx < 129024) {
            int j = widx - 55296;
            int r = j / 18432, jj = j - r * 18432;
            wcvt(rb + r * 36864, gt_rb + r * 18432, jj, 64);
        } else if (widx < 131328) {
            int j = widx - 129024;
            int chunk = j / 576, rem = j % 576;
            int tap = rem >> 6, oc = (rem >> 3) & 7, ws = rem & 7;
            int p = (ws >> 1) + ((ws & 1) << 2);
            int c0 = chunk * 16 + 2 * p;
            gt_wn3[j] = (oc == 0) ? packh2(wn3[c0 * 9 + tap], wn3[(c0 + 1) * 9 + tap]) : 0u;
        } else if (widx < 135424) {
            int j = widx - 131328;
            int branch = j >> 11, rem = j & 2047;
            int kc = rem >> 9, m = (rem >> 3) & 63, ws = rem & 7;
            int p = (ws >> 1) + ((ws & 1) << 2);
            int k0 = kc * 16 + 2 * p;
            const float* W = branch ? gkw1 : dkw1;
            gt_fw1[j] = packh2(W[m * 64 + k0], W[m * 64 + k0 + 1]);
        } else if (widx < 136448) {
            int j = widx - 135424;
            int branch = j >> 9, rem = j & 511;
            int kc = rem >> 7, m = (rem >> 3) & 15, ws = rem & 7;
            int p = (ws >> 1) + ((ws & 1) << 2);
            int k0 = kc * 16 + 2 * p;
            const float* W = branch ? gkw2 : dkw2;
            gt_fw2[j] = (m < 9) ? packh2(W[m * 64 + k0], W[m * 64 + k0 + 1]) : 0u;
        }
    }
}

// ---------------------------------------------------------------------------
// fp16 implicit-GEMM 3x3 conv body: 3-stage cp.async pipeline, one sync/chunk.
// NOC oc-groups per block; `part` = oc-slice index. NOC=1: weights staged once.
// ---------------------------------------------------------------------------
#define CONV_IN_W 2720
#define SMEM_N4 ((3*CONV_IN_W + 3*2304) * 4)   // 60288 (NOC=4, 3 blocks/SM)
#define SMEM_N2 ((3*CONV_IN_W + 3*1152) * 4)   // 46464 (NOC<=2, 4 blocks/SM)

template<int NC, int NOC, bool RELU, bool SKIP, bool WF32, bool WT16>
__device__ __forceinline__ void conv_body(
    u32t* sm, const u32t* __restrict__ in_t, const u32t* __restrict__ wt,
    const float* __restrict__ bias, const float* __restrict__ skip,
    float* __restrict__ outf, u32t* __restrict__ outt,
    int Hd, int Wd, int gx0, int gy0, int b, int part) {
    constexpr int NT  = 256;
    constexpr int W_W = 576 * NOC;
    const int t    = threadIdx.x;
    const int warp = t >> 5, lane = t & 31;
    const int G    = lane >> 2, tig = lane & 3;
    const size_t HW = (size_t)Hd * Wd;
    const u32t smbase = (u32t)__cvta_generic_to_shared(sm);

    int in_src[3]; u32t in_dst[3]; int in_nb[3];
#pragma unroll
    for (int i = 0; i < 3; i++) {
        int u = t + i * NT;
        if (u < 680) {
            int r  = u / 68, h = u - r * 68;
            int xx = h >> 1, hf = h & 1;
            int gy = gy0 + r - 1, gx = gx0 + xx - 1;
            bool ok = (gy >= 0) && (gy < Hd) && (gx >= 0) && (gx < Wd);
            in_src[i] = ((ok ? gy : 0) * Wd + (ok ? gx : 0)) * 8 + hf * 4;
            in_nb[i]  = ok ? 16 : 0;
            in_dst[i] = (u32t)(((r * 34 + xx) * 8 + hf * 4) * 4);
        } else in_nb[i] = -1;
    }

    auto stage = [&](int k, int buf) {
        const u32t* gin = in_t + ((size_t)b * NC + k) * HW * 8;
        const u32t sb = smbase + buf * (CONV_IN_W * 4);
#pragma unroll
        for (int i = 0; i < 3; i++)
            if (in_nb[i] >= 0)
                asm volatile("cp.async.cg.shared.global [%0], [%1], 16, %2;"
                             :: "r"(sb + in_dst[i]), "l"(gin + in_src[i]), "r"(in_nb[i]));
        if (NOC == 1) {
            if (k == 0) {
                const u32t swb = smbase + (u32t)((3 * CONV_IN_W) * 4);
                for (int u = t; u < NC * 144; u += NT)
                    asm volatile("cp.async.cg.shared.global [%0], [%1], 16, 16;"
                                 :: "r"(swb + u * 16), "l"(wt + u * 4));
            }
        } else {
            const u32t swb = smbase + (u32t)((3 * CONV_IN_W + buf * W_W) * 4);
            for (int u = t; u < W_W / 4; u += NT) {
                int tap = u / (NOC * 16), rem = u % (NOC * 16);
                const u32t* src = wt + (size_t)k * 4608 + tap * 512
                                  + part * (NOC * 64) + rem * 4;
                asm volatile("cp.async.cg.shared.global [%0], [%1], 16, 16;"
                             :: "r"(swb + u * 16), "l"(src));
            }
        }
    };

    float d[2][NOC][4];
#pragma unroll
    for (int m = 0; m < 2; m++)
#pragma unroll
        for (int n = 0; n < NOC; n++)
#pragma unroll
            for (int i = 0; i < 4; i++) d[m][n][i] = 0.f;

    stage(0, 0);
    asm volatile("cp.async.commit_group;");
    stage(1, 1);
    asm volatile("cp.async.commit_group;");

    for (int k = 0; k < NC; k++) {
        if (k + 1 < NC) asm volatile("cp.async.wait_group 1;");
        else            asm volatile("cp.async.wait_group 0;");
        __syncthreads();
        if (k + 2 < NC) {
            stage(k + 2, (k + 2) % 3);
            asm volatile("cp.async.commit_group;");
        }
        const u32t* bin = sm + (k % 3) * CONV_IN_W;
        const u32t* bw  = (NOC == 1) ? sm + 3 * CONV_IN_W + k * 576
                                     : sm + 3 * CONV_IN_W + (k % 3) * W_W;
#pragma unroll
        for (int tap = 0; tap < 9; tap++) {
            const int ky = tap / 3, kx = tap % 3;
            uint2 a[2][2];
#pragma unroll
            for (int m = 0; m < 2; m++) {
                const int xx = m * 16 + G + kx;
                a[m][0] = *(const uint2*)&bin[((warp + ky) * 34 + xx) * 8 + 2 * tig];
                a[m][1] = *(const uint2*)&bin[((warp + ky) * 34 + xx + 8) * 8 + 2 * tig];
            }
#pragma unroll
            for (int n = 0; n < NOC; n++) {
                uint2 q = *(const uint2*)&bw[(tap * (8 * NOC) + n * 8 + G) * 8 + 2 * tig];
#pragma unroll
                for (int m = 0; m < 2; m++)
                    mma_f16(d[m][n], a[m][0].x, a[m][1].x, a[m][0].y, a[m][1].y,
                            q.x, q.y);
            }
        }
    }

    // ---- epilogue ----
    const int gy = gy0 + warp;
    if (NOC == 1) {
        if (tig == 0) {
            float bv = __ldg(&bias[0]);
#pragma unroll
            for (int m = 0; m < 2; m++) {
                const int x = gx0 + m * 16 + G;
                float v0 = d[m][0][0] + bv;
                float v2 = d[m][0][2] + bv;
                if (RELU) { v0 = fmaxf(v0, 0.f); v2 = fmaxf(v2, 0.f); }
                outf[(size_t)b * HW + (size_t)gy * Wd + x]     = v0;
                outf[(size_t)b * HW + (size_t)gy * Wd + x + 8] = v2;
            }
        }
        return;
    }
#pragma unroll
    for (int m = 0; m < 2; m++) {
        const int x = gx0 + m * 16 + G;
#pragma unroll
        for (int n = 0; n < NOC; n++) {
            const int ng = part * NOC + n;
            const int oc = ng * 8 + 2 * tig;
            float b0v = __ldg(&bias[oc]);
            float b1v = __ldg(&bias[oc + 1]);
            float v0 = d[m][n][0] + b0v;
            float v1 = d[m][n][1] + b1v;
            float v2 = d[m][n][2] + b0v;
            float v3 = d[m][n][3] + b1v;
            size_t f0 = (((size_t)b * 64 + oc) * Hd + gy) * Wd + x;
            size_t f1 = f0 + HW;
            if (SKIP) {
                v0 += skip[f0];     v1 += skip[f1];
                v2 += skip[f0 + 8]; v3 += skip[f1 + 8];
            }
            if (RELU) {
                v0 = fmaxf(v0, 0.f); v1 = fmaxf(v1, 0.f);
                v2 = fmaxf(v2, 0.f); v3 = fmaxf(v3, 0.f);
            }
            if (WF32) {
                outf[f0] = v0; outf[f1] = v1; outf[f0 + 8] = v2; outf[f1 + 8] = v3;
            }
            if (WT16) {
                int slot = 2 * tig + (ng & 1);
                size_t tb = (((size_t)b * 4 + (ng >> 1)) * HW + (size_t)gy * Wd + x) * 8;
                outt[tb + slot]      = packh2(v0, v1);
                outt[tb + 64 + slot] = packh2(v2, v3);
            }
        }
    }
}

// ---------------------------------------------------------------------------
// stage kernels: stage1 = NOC=4 halves (3 blk/SM); stage2/3/r4 = NOC=2 (4 blk/SM)
// ---------------------------------------------------------------------------
__global__ __launch_bounds__(256, 3)
void k_stage1(const float* __restrict__ wn_b1, const float* __restrict__ rb_b) {
    extern __shared__ u32t sm[];
    int bid = blockIdx.x;
    if (bid < 1024) {
        int bx = bid & 7, by = (bid >> 3) & 31, b = (bid >> 8) & 1, oh = bid >> 9;
        conv_body<8, 4, true, false, false, true>(sm, gt_in0, gt_wn1, wn_b1,
            nullptr, nullptr, gt_wm1, H2_, W2_, bx * 32, by * 8, b, oh);
    } else {
        int j = bid - 1024;
        int bx = j & 3, by = (j >> 2) & 15, b = (j >> 6) & 1, oh = j >> 7;
        conv_body<4, 4, true, false, false, true>(sm, gt_inlo, gt_rb, rb_b,
            nullptr, nullptr, gt_r1, H1_, W1_, bx * 32, by * 8, b, oh);
    }
}

__global__ __launch_bounds__(256, 4)
void k_stage2(const float* __restrict__ wn_b2, const float* __restrict__ rb_b,
              const float* __restrict__ inputs) {
    extern __shared__ u32t sm[];
    int bid = blockIdx.x;
    if (bid < 2048) {
        int bx = bid & 7, by = (bid >> 3) & 31, b = (bid >> 8) & 1, oq = bid >> 9;
        conv_body<4, 2, true, false, false, true>(sm, gt_wm1, gt_wn2, wn_b2,
            nullptr, nullptr, gt_wm2, H2_, W2_, bx * 32, by * 8, b, oq);
    } else {
        int j = bid - 2048;
        int bx = j & 3, by = (j >> 2) & 15, b = (j >> 6) & 1, oq = j >> 7;
        conv_body<4, 2, false, true, true, true>(sm, gt_r1, gt_rb + 1 * 18432, rb_b + 64,
            inputs, g_r2, gt_r2, H1_, W1_, bx * 32, by * 8, b, oq);
    }
}

__global__ __launch_bounds__(256, 4)
void k_stage3(const float* __restrict__ wn_b3, const float* __restrict__ rb_b) {
    extern __shared__ u32t sm[];
    int bid = blockIdx.x;
    if (bid < 512) {
        int bx = bid & 7, by = (bid >> 3) & 31, b = bid >> 8;
        conv_body<4, 1, false, false, true, false>(sm, gt_wm2, gt_wn3, wn_b3,
            nullptr, g_wmap, nullptr, H2_, W2_, bx * 32, by * 8, b, 0);
    } else {
        int j = bid - 512;
        int bx = j & 3, by = (j >> 2) & 15, b = (j >> 6) & 1, oq = j >> 7;
        conv_body<4, 2, true, false, false, true>(sm, gt_r2, gt_rb + 2 * 18432, rb_b + 128,
            nullptr, nullptr, gt_r3, H1_, W1_, bx * 32, by * 8, b, oq);
    }
}

__global__ __launch_bounds__(256, 4)
void k_r4(const float* __restrict__ rb_b) {
    extern __shared__ u32t sm[];
    int j = blockIdx.x;
    int bx = j & 3, by = (j >> 2) & 15, b = (j >> 6) & 1, oq = j >> 7;
    conv_body<4, 2, false, true, true, false>(sm, gt_r3, gt_rb + 3 * 18432, rb_b + 192,
        g_r2, g_r3, nullptr, H1_, W1_, bx * 32, by * 8, b, oq);
}

// ---------------------------------------------------------------------------
// fuse: fp16 hidden + logits GEMMs; parallelized softmax/tanh tail.
// ---------------------------------------------------------------------------
__global__ __launch_bounds__(256)
void fuse_kernel(const float* __restrict__ dkb1, const float* __restrict__ dkb2,
                 const float* __restrict__ gkb1, const float* __restrict__ gkb2,
                 const float* __restrict__ aff) {
    __shared__ u32t   s_x[8][64][8];
    __shared__ __half s_h[64][72];
    __shared__ float  s_l[2][9][64];
    __shared__ float  s_e[2][9][64];
    __shared__ float  s_is[2][64];
    __shared__ float  s_f[9][64];

    const int b    = blockIdx.y;
    const int px0  = blockIdx.x * 64;
    const int t    = threadIdx.x;
    const int warp = t >> 5, lane = t & 31;
    const int G    = lane >> 2, tig = lane & 3;
    const int mt   = warp & 3, nh = warp >> 2;
    const int c0   = mt * 16;

    {
        const u32t smb = (u32t)__cvta_generic_to_shared(&s_x[0][0][0]);
        for (int u = t; u < 1024; u += 256) {
            int ch = u >> 7, rem = u & 127;
            int px = rem >> 1, hf = rem & 1;
            const u32t* src = gt_in0 + (((size_t)b * 8 + ch) * HW2_ + px0 + px) * 8 + hf * 4;
            asm volatile("cp.async.cg.shared.global [%0], [%1], 16, 16;"
                         :: "r"(smb + (u32t)(((ch * 64 + px) * 8 + hf * 4) * 4)), "l"(src));
        }
        asm volatile("cp.async.commit_group;");
        asm volatile("cp.async.wait_group 0;");
    }
    __syncthreads();

#pragma unroll
    for (int branch = 0; branch < 2; branch++) {
        const float* B1v = branch ? gkb1 : dkb1;
        const float* B2v = branch ? gkb2 : dkb2;
        const u32t* w1 = gt_fw1 + branch * 2048;
        const u32t* w2 = gt_fw2 + branch * 512;

        if (branch) __syncthreads();

        float d[4][4];
#pragma unroll
        for (int nc = 0; nc < 4; nc++)
#pragma unroll
            for (int i = 0; i < 4; i++) d[nc][i] = 0.f;
#pragma unroll
        for (int kc = 0; kc < 4; kc++) {
            uint2 q0 = *(const uint2*)&w1[((kc * 64) + c0 + G)     * 8 + 2 * tig];
            uint2 q1 = *(const uint2*)&w1[((kc * 64) + c0 + G + 8) * 8 + 2 * tig];
#pragma unroll
            for (int nc = 0; nc < 4; nc++) {
                int px = nh * 32 + nc * 8 + G;
                uint2 bb = *(const uint2*)&s_x[branch * 4 + kc][px][2 * tig];
                mma_f16(d[nc], q0.x, q1.x, q0.y, q1.y, bb.x, bb.y);
            }
        }
        float bv0 = __ldg(&B1v[c0 + G]);
        float bv8 = __ldg(&B1v[c0 + G + 8]);
#pragma unroll
        for (int nc = 0; nc < 4; nc++) {
            int px = nh * 32 + nc * 8 + 2 * tig;
            s_h[px][c0 + G]         = __float2half_rn(fmaxf(d[nc][0] + bv0, 0.f));
            s_h[px + 1][c0 + G]     = __float2half_rn(fmaxf(d[nc][1] + bv0, 0.f));
            s_h[px][c0 + G + 8]     = __float2half_rn(fmaxf(d[nc][2] + bv8, 0.f));
            s_h[px + 1][c0 + G + 8] = __float2half_rn(fmaxf(d[nc][3] + bv8, 0.f));
        }
        __syncthreads();

        {
            const int n0 = warp * 8;
            float d2[4] = {0.f, 0.f, 0.f, 0.f};
#pragma unroll
            for (int kc = 0; kc < 4; kc++) {
                uint2 q0 = *(const uint2*)&w2[((kc * 16) + G)     * 8 + 2 * tig];
                uint2 q1 = *(const uint2*)&w2[((kc * 16) + G + 8) * 8 + 2 * tig];
                u32t b0 = *(const u32t*)&s_h[n0 + G][kc * 16 + 2 * tig];
                u32t b1 = *(const u32t*)&s_h[n0 + G][kc * 16 + 2 * tig + 8];
                mma_f16(d2, q0.x, q1.x, q0.y, q1.y, b0, b1);
            }
            float bj = __ldg(&B2v[G]);
            s_l[branch][G][n0 + 2 * tig]     = d2[0] + bj;
            s_l[branch][G][n0 + 2 * tig + 1] = d2[1] + bj;
            if (G == 0) {
                float b8 = __ldg(&B2v[8]);
                s_l[branch][8][n0 + 2 * tig]     = d2[2] + b8;
                s_l[branch][8][n0 + 2 * tig + 1] = d2[3] + b8;
            }
        }
    }
    __syncthreads();

    // phase A: per-(branch,px) softmax exps on 128 threads
    if (t < 128) {
        int br = t >> 6, px = t & 63;
        float mx = -1e30f;
#pragma unroll
        for (int j = 0; j < 9; j++) mx = fmaxf(mx, s_l[br][j][px]);
        float s = 0.f;
#pragma unroll
        for (int j = 0; j < 9; j++) {
            float e = expf(s_l[br][j][px] - mx);
            s_e[br][j][px] = e;
            s += e;
        }
        s_is[br][px] = 1.f / s;
    }
    __syncthreads();

    // phase B: fuse-combine + tanh over all 256 threads (576 items)
    {
        float affv = __ldg(&aff[0]) + 1e-8f;
        for (int idx = t; idx < 576; idx += 256) {
            int j = idx >> 6, px = idx & 63;
            float wm = g_wmap[(size_t)b * HW2_ + px0 + px];
            float fv = wm * (s_e[0][j][px] * s_is[0][px])
                     + (1.f - wm) * (s_e[1][j][px] * s_is[1][px]);
            s_f[j][px] = tanhf(fv) / affv;
        }
    }
    __syncthreads();

    // phase C: L1 normalize + write
    if (t < 64) {
        float asum = 0.f;
#pragma unroll
        for (int j = 0; j < 9; j++) asum += fabsf(s_f[j][t]);
        float inv_ks = 1.f / fmaxf(asum + 1e-4f, 1.0f);
#pragma unroll
        for (int j = 0; j < 9; j++)
            g_fuse[((size_t)b * 9 + j) * HW2_ + px0 + t] = s_f[j][t] * inv_ks;
    }
}

// ---------------------------------------------------------------------------
// gather with fused bilinear upsample — 8 channels per round
// ---------------------------------------------------------------------------
__global__ __launch_bounds__(256)
void gather_kernel(float* __restrict__ out) {
    __shared__ float s_r3[8][8][21];
    __shared__ float s_up[8][12][37];
    const int b   = blockIdx.z;
    const int gx0 = blockIdx.x * 32;
    const int gy0 = blockIdx.y * 8;
    const int t   = threadIdx.x;
    const int xl  = t & 31, yl = t >> 5;
    const int gx  = gx0 + xl, gy = gy0 + yl;
    const int ly0 = gy0 / 2 - 2, lx0 = gx0 / 2 - 2;

    float f[9];
#pragma unroll
    for (int j = 0; j < 9; j++)
        f[j] = g_fuse[((size_t)b * 9 + j) * HW2_ + gy * W2_ + gx];

    for (int c0 = 0; c0 < 64; c0 += 8) {
        __syncthreads();
        for (int idx = t; idx < 1280; idx += 256) {
            int cl = idx / 160, rem = idx - cl * 160;
            int r = rem / 20, cc = rem - r * 20;
            int yy = min(max(ly0 + r, 0), 127);
            int xx = min(max(lx0 + cc, 0), 127);
            s_r3[cl][r][cc] = g_r3[((size_t)b * 64 + c0 + cl) * HW1_ + yy * 128 + xx];
        }
        __syncthreads();
        for (int idx = t; idx < 432; idx += 256) {
            int r = idx / 36, cc = idx - r * 36;
            int Y = gy0 + r - 2, X = gx0 + cc - 2;
            bool ok = (Y >= 0) && (Y < H2_) && (X >= 0) && (X < W2_);
            int m = Y >> 1, ya, yb; float wya, wyb;
            if (Y & 1) { ya = m; yb = min(m + 1, 127); wya = 0.75f; wyb = 0.25f; }
            else       { ya = max(m - 1, 0); yb = m;   wya = 0.25f; wyb = 0.75f; }
            int n = X >> 1, xa, xb; float wxa, wxb;
            if (X & 1) { xa = n; xb = min(n + 1, 127); wxa = 0.75f; wxb = 0.25f; }
            else       { xa = max(n - 1, 0); xb = n;   wxa = 0.25f; wxb = 0.75f; }
            int iya = min(max(ya - ly0, 0), 7), iyb = min(max(yb - ly0, 0), 7);
            int ixa = min(max(xa - lx0, 0), 20), ixb = min(max(xb - lx0, 0), 20);
            float waa = wya * wxa, wab = wya * wxb, wba = wyb * wxa, wbb = wyb * wxb;
#pragma unroll
            for (int cl = 0; cl < 8; cl++) {
                float v = waa * s_r3[cl][iya][ixa] + wab * s_r3[cl][iya][ixb]
                        + wba * s_r3[cl][iyb][ixa] + wbb * s_r3[cl][iyb][ixb];
                s_up[cl][r][cc] = ok ? v : 0.f;
            }
        }
        __syncthreads();
#pragma unroll
        for (int cl = 0; cl < 8; cl++) {
            float acc = 0.f;
#pragma unroll
            for (int ky = 0; ky < 3; ky++)
#pragma unroll
                for (int kx = 0; kx < 3; kx++)
                    acc += f[ky * 3 + kx] * s_up[cl][yl + 2 * ky][xl + 2 * kx];
            out[(((size_t)b * 64 + c0 + cl) * H2_ + gy) * W2_ + gx] = acc;
        }
    }
}

// ---------------------------------------------------------------------------
extern "C" void kernel_launch(void* const* d_in, const int* in_sizes, int n_in,
                              void* d_out, int out_size) {
    const float* depth  = (const float*)d_in[0];
    const float* guide  = (const float*)d_in[1];
    const float* inputs = (const float*)d_in[2];
    const float* dk_w1  = (const float*)d_in[3];
    const float* dk_b1  = (const float*)d_in[4];
    const float* dk_w2  = (const float*)d_in[5];
    const float* dk_b2  = (const float*)d_in[6];
    const float* gk_w1  = (const float*)d_in[7];
    const float* gk_b1  = (const float*)d_in[8];
    const float* gk_w2  = (const float*)d_in[9];
    const float* gk_b2  = (const float*)d_in[10];
    const float* wn_w1  = (const float*)d_in[11];
    const float* wn_b1  = (const float*)d_in[12];
    const float* wn_w2  = (const float*)d_in[13];
    const float* wn_b2  = (const float*)d_in[14];
    const float* wn_w3  = (const float*)d_in[15];
    const float* wn_b3  = (const float*)d_in[16];
    const float* rb_w   = (const float*)d_in[17];
    const float* rb_b   = (const float*)d_in[18];
    const float* aff    = (const float*)d_in[19];
    float* out = (float*)d_out;

    cudaFuncSetAttribute(k_stage1, cudaFuncAttributeMaxDynamicSharedMemorySize, SMEM_N4);
    cudaFuncSetAttribute(k_stage2, cudaFuncAttributeMaxDynamicSharedMemorySize, SMEM_N2);
    cudaFuncSetAttribute(k_stage3, cudaFuncAttributeMaxDynamicSharedMemorySize, SMEM_N2);
    cudaFuncSetAttribute(k_r4,     cudaFuncAttributeMaxDynamicSharedMemorySize, SMEM_N2);

    // prep (inputs + all weights in one launch)
    k_prep<<<(NPI_ + 136448 + 255) / 256, 256>>>(depth, guide, inputs,
                                                 wn_w1, wn_w2, rb_w, wn_w3,
                                                 dk_w1, gk_w1, dk_w2, gk_w2);

    // hybrid: stage1 oc-halves (3 blk/SM); stage2/3 oc-quarters (4 blk/SM)
    k_stage1<<<1280, 256, SMEM_N4>>>(wn_b1, rb_b);
    k_stage2<<<2560, 256, SMEM_N2>>>(wn_b2, rb_b, inputs);
    k_stage3<<<1024, 256, SMEM_N2>>>(wn_b3, rb_b);

    // fuse then final residual conv
    dim3 gfuse(HW2_ / 64, B_);
    fuse_kernel<<<gfuse, 256>>>(dk_b1, dk_b2, gk_b1, gk_b2, aff);
    k_r4<<<512, 256, SMEM_N2>>>(rb_b);

    // fused upsample + gather
    dim3 ghi8(W2_ / 32, H2_ / 8, B_);
    gather_kernel<<<ghi8, 256>>>(out);
}

// round 17
// speedup vs baseline: 1.0283x; 1.0283x over previous
#include <cuda_runtime.h>
#include <cuda_fp16.h>
#include <math.h>

#define B_  2
#define C_  64
#define H2_ 256
#define W2_ 256
#define HW2_ (H2_*W2_)
#define H1_ 128
#define W1_ 128
#define HW1_ (H1_*W1_)
#define KK_ 9

typedef unsigned long long u64t;
typedef unsigned int u32t;

__device__ __forceinline__ void mma_f16(float* d, u32t a0, u32t a1, u32t a2, u32t a3,
                                        u32t b0, u32t b1) {
    asm("mma.sync.aligned.m16n8k16.row.col.f32.f16.f16.f32 "
        "{%0,%1,%2,%3},{%4,%5,%6,%7},{%8,%9},{%0,%1,%2,%3};"
        : "+f"(d[0]), "+f"(d[1]), "+f"(d[2]), "+f"(d[3])
        : "r"(a0), "r"(a1), "r"(a2), "r"(a3), "r"(b0), "r"(b1));
}
__device__ __forceinline__ u32t packh2(float lo, float hi) {
    __half2 h = __floats2half2_rn(lo, hi);
    return *(u32t*)&h;
}

// ---------------- scratch ----------------
__device__ float g_wmap[B_*HW2_];
__device__ float g_fuse[B_*KK_*HW2_];
__device__ float g_r2[B_*C_*HW1_];
__device__ float g_r3[B_*C_*HW1_];

// fp16 pair-interleaved buffers: [b][chunk16][px][8 words]
__device__ u32t gt_in0[B_*8*HW2_*8];
__device__ u32t gt_wm1[B_*4*HW2_*8];
__device__ u32t gt_wm2[B_*4*HW2_*8];
__device__ u32t gt_inlo[B_*4*HW1_*8];
__device__ u32t gt_r1[B_*4*HW1_*8];
__device__ u32t gt_r2[B_*4*HW1_*8];
__device__ u32t gt_r3[B_*4*HW1_*8];
// fp16 weights: [chunk16][tap][oc][8 words]
__device__ u32t gt_wn1[8*9*64*8];
__device__ u32t gt_wn2[4*9*64*8];
__device__ u32t gt_rb [4*4*9*64*8];
__device__ u32t gt_wn3[4*9*8*8];
// fp16 fuse weights
__device__ u32t gt_fw1[2*4*64*8];
__device__ u32t gt_fw2[2*4*16*8];

// ---------------------------------------------------------------------------
// merged prep: inputs + all weights -> fp16 pair-interleaved
// ---------------------------------------------------------------------------
#define NPI_ (B_*8*HW2_ + B_*4*HW1_)

__device__ __forceinline__ void wcvt(const float* __restrict__ w, u32t* __restrict__ o,
                                     int widx, int CIN) {
    int ws  = widx & 7;
    int oc  = (widx >> 3) & 63;
    int rem = widx >> 9;
    int tap = rem % 9, chunk = rem / 9;
    int p   = (ws >> 1) + ((ws & 1) << 2);
    int c0  = chunk * 16 + 2 * p;
    o[widx] = packh2(w[(oc * CIN + c0) * 9 + tap], w[(oc * CIN + c0 + 1) * 9 + tap]);
}

__global__ void k_prep(const float* __restrict__ depth, const float* __restrict__ guide,
                       const float* __restrict__ inputs,
                       const float* __restrict__ wn1, const float* __restrict__ wn2,
                       const float* __restrict__ rb,  const float* __restrict__ wn3,
                       const float* __restrict__ dkw1, const float* __restrict__ gkw1,
                       const float* __restrict__ dkw2, const float* __restrict__ gkw2) {
    int idx = blockIdx.x * 256 + threadIdx.x;
    const int N0 = B_ * 8 * HW2_;
    if (idx < N0) {
        int px = idx & (HW2_ - 1);
        int ch = (idx >> 16) & 7;
        int b  = idx >> 19;
        const float* src = (ch < 4 ? depth : guide) + ((size_t)b * 64 + (ch & 3) * 16) * HW2_ + px;
        u32t w[8];
#pragma unroll
        for (int ws = 0; ws < 8; ws++) {
            int p = (ws >> 1) + ((ws & 1) << 2);
            w[ws] = packh2(src[(size_t)(2 * p) * HW2_], src[(size_t)(2 * p + 1) * HW2_]);
        }
        *(uint4*)&gt_in0[(size_t)idx * 8]     = make_uint4(w[0], w[1], w[2], w[3]);
        *(uint4*)&gt_in0[(size_t)idx * 8 + 4] = make_uint4(w[4], w[5], w[6], w[7]);
    } else if (idx < NPI_) {
        int j = idx - N0;
        int px = j & (HW1_ - 1);
        int ch = (j >> 14) & 3;
        int b  = j >> 16;
        const float* src = inputs + ((size_t)b * 64 + ch * 16) * HW1_ + px;
        u32t w[8];
#pragma unroll
        for (int ws = 0; ws < 8; ws++) {
            int p = (ws >> 1) + ((ws & 1) << 2);
            w[ws] = packh2(src[(size_t)(2 * p) * HW1_], src[(size_t)(2 * p + 1) * HW1_]);
        }
        *(uint4*)&gt_inlo[(size_t)j * 8]     = make_uint4(w[0], w[1], w[2], w[3]);
        *(uint4*)&gt_inlo[(size_t)j * 8 + 4] = make_uint4(w[4], w[5], w[6], w[7]);
    } else {
        int widx = idx - NPI_;
        if (widx < 36864) {
            wcvt(wn1, gt_wn1, widx, 128);
        } else if (widx < 55296) {
            wcvt(wn2, gt_wn2, widx - 36864, 64);
        } else if (widx < 129024) {
            int j = widx - 55296;
            int r = j / 18432, jj = j - r * 18432;
            wcvt(rb + r * 36864, gt_rb + r * 18432, jj, 64);
        } else if (widx < 131328) {
            int j = widx - 129024;
            int chunk = j / 576, rem = j % 576;
            int tap = rem >> 6, oc = (rem >> 3) & 7, ws = rem & 7;
            int p = (ws >> 1) + ((ws & 1) << 2);
            int c0 = chunk * 16 + 2 * p;
            gt_wn3[j] = (oc == 0) ? packh2(wn3[c0 * 9 + tap], wn3[(c0 + 1) * 9 + tap]) : 0u;
        } else if (widx < 135424) {
            int j = widx - 131328;
            int branch = j >> 11, rem = j & 2047;
            int kc = rem >> 9, m = (rem >> 3) & 63, ws = rem & 7;
            int p = (ws >> 1) + ((ws & 1) << 2);
            int k0 = kc * 16 + 2 * p;
            const float* W = branch ? gkw1 : dkw1;
            gt_fw1[j] = packh2(W[m * 64 + k0], W[m * 64 + k0 + 1]);
        } else if (widx < 136448) {
            int j = widx - 135424;
            int branch = j >> 9, rem = j & 511;
            int kc = rem >> 7, m = (rem >> 3) & 15, ws = rem & 7;
            int p = (ws >> 1) + ((ws & 1) << 2);
            int k0 = kc * 16 + 2 * p;
            const float* W = branch ? gkw2 : dkw2;
            gt_fw2[j] = (m < 9) ? packh2(W[m * 64 + k0], W[m * 64 + k0 + 1]) : 0u;
        }
    }
}

// ---------------------------------------------------------------------------
// fp16 implicit-GEMM 3x3 conv body: 3-stage cp.async pipeline, one sync/chunk.
// NOC oc-groups per block; `part` = oc-slice index. NOC=1: weights staged once.
// ---------------------------------------------------------------------------
#define CONV_IN_W 2720
#define SMEM_N4 ((3*CONV_IN_W + 3*2304) * 4)   // 60288 (NOC=4, 3 blocks/SM)
#define SMEM_N2 ((3*CONV_IN_W + 3*1152) * 4)   // 46464 (NOC<=2, 4 blocks/SM)

template<int NC, int NOC, bool RELU, bool SKIP, bool WF32, bool WT16>
__device__ __forceinline__ void conv_body(
    u32t* sm, const u32t* __restrict__ in_t, const u32t* __restrict__ wt,
    const float* __restrict__ bias, const float* __restrict__ skip,
    float* __restrict__ outf, u32t* __restrict__ outt,
    int Hd, int Wd, int gx0, int gy0, int b, int part) {
    constexpr int NT  = 256;
    constexpr int W_W = 576 * NOC;
    const int t    = threadIdx.x;
    const int warp = t >> 5, lane = t & 31;
    const int G    = lane >> 2, tig = lane & 3;
    const size_t HW = (size_t)Hd * Wd;
    const u32t smbase = (u32t)__cvta_generic_to_shared(sm);

    int in_src[3]; u32t in_dst[3]; int in_nb[3];
#pragma unroll
    for (int i = 0; i < 3; i++) {
        int u = t + i * NT;
        if (u < 680) {
            int r  = u / 68, h = u - r * 68;
            int xx = h >> 1, hf = h & 1;
            int gy = gy0 + r - 1, gx = gx0 + xx - 1;
            bool ok = (gy >= 0) && (gy < Hd) && (gx >= 0) && (gx < Wd);
            in_src[i] = ((ok ? gy : 0) * Wd + (ok ? gx : 0)) * 8 + hf * 4;
            in_nb[i]  = ok ? 16 : 0;
            in_dst[i] = (u32t)(((r * 34 + xx) * 8 + hf * 4) * 4);
        } else in_nb[i] = -1;
    }

    auto stage = [&](int k, int buf) {
        const u32t* gin = in_t + ((size_t)b * NC + k) * HW * 8;
        const u32t sb = smbase + buf * (CONV_IN_W * 4);
#pragma unroll
        for (int i = 0; i < 3; i++)
            if (in_nb[i] >= 0)
                asm volatile("cp.async.cg.shared.global [%0], [%1], 16, %2;"
                             :: "r"(sb + in_dst[i]), "l"(gin + in_src[i]), "r"(in_nb[i]));
        if (NOC == 1) {
            if (k == 0) {
                const u32t swb = smbase + (u32t)((3 * CONV_IN_W) * 4);
                for (int u = t; u < NC * 144; u += NT)
                    asm volatile("cp.async.cg.shared.global [%0], [%1], 16, 16;"
                                 :: "r"(swb + u * 16), "l"(wt + u * 4));
            }
        } else {
            const u32t swb = smbase + (u32t)((3 * CONV_IN_W + buf * W_W) * 4);
            for (int u = t; u < W_W / 4; u += NT) {
                int tap = u / (NOC * 16), rem = u % (NOC * 16);
                const u32t* src = wt + (size_t)k * 4608 + tap * 512
                                  + part * (NOC * 64) + rem * 4;
                asm volatile("cp.async.cg.shared.global [%0], [%1], 16, 16;"
                             :: "r"(swb + u * 16), "l"(src));
            }
        }
    };

    float d[2][NOC][4];
#pragma unroll
    for (int m = 0; m < 2; m++)
#pragma unroll
        for (int n = 0; n < NOC; n++)
#pragma unroll
            for (int i = 0; i < 4; i++) d[m][n][i] = 0.f;

    stage(0, 0);
    asm volatile("cp.async.commit_group;");
    stage(1, 1);
    asm volatile("cp.async.commit_group;");

    for (int k = 0; k < NC; k++) {
        if (k + 1 < NC) asm volatile("cp.async.wait_group 1;");
        else            asm volatile("cp.async.wait_group 0;");
        __syncthreads();
        if (k + 2 < NC) {
            stage(k + 2, (k + 2) % 3);
            asm volatile("cp.async.commit_group;");
        }
        const u32t* bin = sm + (k % 3) * CONV_IN_W;
        const u32t* bw  = (NOC == 1) ? sm + 3 * CONV_IN_W + k * 576
                                     : sm + 3 * CONV_IN_W + (k % 3) * W_W;
#pragma unroll
        for (int tap = 0; tap < 9; tap++) {
            const int ky = tap / 3, kx = tap % 3;
            uint2 a[2][2];
#pragma unroll
            for (int m = 0; m < 2; m++) {
                const int xx = m * 16 + G + kx;
                a[m][0] = *(const uint2*)&bin[((warp + ky) * 34 + xx) * 8 + 2 * tig];
                a[m][1] = *(const uint2*)&bin[((warp + ky) * 34 + xx + 8) * 8 + 2 * tig];
            }
#pragma unroll
            for (int n = 0; n < NOC; n++) {
                uint2 q = *(const uint2*)&bw[(tap * (8 * NOC) + n * 8 + G) * 8 + 2 * tig];
#pragma unroll
                for (int m = 0; m < 2; m++)
                    mma_f16(d[m][n], a[m][0].x, a[m][1].x, a[m][0].y, a[m][1].y,
                            q.x, q.y);
            }
        }
    }

    // ---- epilogue ----
    const int gy = gy0 + warp;
    if (NOC == 1) {
        if (tig == 0) {
            float bv = __ldg(&bias[0]);
#pragma unroll
            for (int m = 0; m < 2; m++) {
                const int x = gx0 + m * 16 + G;
                float v0 = d[m][0][0] + bv;
                float v2 = d[m][0][2] + bv;
                if (RELU) { v0 = fmaxf(v0, 0.f); v2 = fmaxf(v2, 0.f); }
                outf[(size_t)b * HW + (size_t)gy * Wd + x]     = v0;
                outf[(size_t)b * HW + (size_t)gy * Wd + x + 8] = v2;
            }
        }
        return;
    }
#pragma unroll
    for (int m = 0; m < 2; m++) {
        const int x = gx0 + m * 16 + G;
#pragma unroll
        for (int n = 0; n < NOC; n++) {
            const int ng = part * NOC + n;
            const int oc = ng * 8 + 2 * tig;
            float b0v = __ldg(&bias[oc]);
            float b1v = __ldg(&bias[oc + 1]);
            float v0 = d[m][n][0] + b0v;
            float v1 = d[m][n][1] + b1v;
            float v2 = d[m][n][2] + b0v;
            float v3 = d[m][n][3] + b1v;
            size_t f0 = (((size_t)b * 64 + oc) * Hd + gy) * Wd + x;
            size_t f1 = f0 + HW;
            if (SKIP) {
                v0 += skip[f0];     v1 += skip[f1];
                v2 += skip[f0 + 8]; v3 += skip[f1 + 8];
            }
            if (RELU) {
                v0 = fmaxf(v0, 0.f); v1 = fmaxf(v1, 0.f);
                v2 = fmaxf(v2, 0.f); v3 = fmaxf(v3, 0.f);
            }
            if (WF32) {
                outf[f0] = v0; outf[f1] = v1; outf[f0 + 8] = v2; outf[f1 + 8] = v3;
            }
            if (WT16) {
                int slot = 2 * tig + (ng & 1);
                size_t tb = (((size_t)b * 4 + (ng >> 1)) * HW + (size_t)gy * Wd + x) * 8;
                outt[tb + slot]      = packh2(v0, v1);
                outt[tb + 64 + slot] = packh2(v2, v3);
            }
        }
    }
}

// ---------------------------------------------------------------------------
// stage kernels: stage1/2 = NOC=4 halves (3 blk/SM); stage3/r4 = NOC=2 (4 blk/SM)
// ---------------------------------------------------------------------------
__global__ __launch_bounds__(256, 3)
void k_stage1(const float* __restrict__ wn_b1, const float* __restrict__ rb_b) {
    extern __shared__ u32t sm[];
    int bid = blockIdx.x;
    if (bid < 1024) {
        int bx = bid & 7, by = (bid >> 3) & 31, b = (bid >> 8) & 1, oh = bid >> 9;
        conv_body<8, 4, true, false, false, true>(sm, gt_in0, gt_wn1, wn_b1,
            nullptr, nullptr, gt_wm1, H2_, W2_, bx * 32, by * 8, b, oh);
    } else {
        int j = bid - 1024;
        int bx = j & 3, by = (j >> 2) & 15, b = (j >> 6) & 1, oh = j >> 7;
        conv_body<4, 4, true, false, false, true>(sm, gt_inlo, gt_rb, rb_b,
            nullptr, nullptr, gt_r1, H1_, W1_, bx * 32, by * 8, b, oh);
    }
}

__global__ __launch_bounds__(256, 3)
void k_stage2(const float* __restrict__ wn_b2, const float* __restrict__ rb_b,
              const float* __restrict__ inputs) {
    extern __shared__ u32t sm[];
    int bid = blockIdx.x;
    if (bid < 1024) {
        int bx = bid & 7, by = (bid >> 3) & 31, b = (bid >> 8) & 1, oh = bid >> 9;
        conv_body<4, 4, true, false, false, true>(sm, gt_wm1, gt_wn2, wn_b2,
            nullptr, nullptr, gt_wm2, H2_, W2_, bx * 32, by * 8, b, oh);
    } else {
        int j = bid - 1024;
        int bx = j & 3, by = (j >> 2) & 15, b = (j >> 6) & 1, oh = j >> 7;
        conv_body<4, 4, false, true, true, true>(sm, gt_r1, gt_rb + 1 * 18432, rb_b + 64,
            inputs, g_r2, gt_r2, H1_, W1_, bx * 32, by * 8, b, oh);
    }
}

__global__ __launch_bounds__(256, 4)
void k_stage3(const float* __restrict__ wn_b3, const float* __restrict__ rb_b) {
    extern __shared__ u32t sm[];
    int bid = blockIdx.x;
    if (bid < 512) {
        int bx = bid & 7, by = (bid >> 3) & 31, b = bid >> 8;
        conv_body<4, 1, false, false, true, false>(sm, gt_wm2, gt_wn3, wn_b3,
            nullptr, g_wmap, nullptr, H2_, W2_, bx * 32, by * 8, b, 0);
    } else {
        int j = bid - 512;
        int bx = j & 3, by = (j >> 2) & 15, b = (j >> 6) & 1, oq = j >> 7;
        conv_body<4, 2, true, false, false, true>(sm, gt_r2, gt_rb + 2 * 18432, rb_b + 128,
            nullptr, nullptr, gt_r3, H1_, W1_, bx * 32, by * 8, b, oq);
    }
}

__global__ __launch_bounds__(256, 4)
void k_r4(const float* __restrict__ rb_b) {
    extern __shared__ u32t sm[];
    int j = blockIdx.x;
    int bx = j & 3, by = (j >> 2) & 15, b = (j >> 6) & 1, oq = j >> 7;
    conv_body<4, 2, false, true, true, false>(sm, gt_r3, gt_rb + 3 * 18432, rb_b + 192,
        g_r2, g_r3, nullptr, H1_, W1_, bx * 32, by * 8, b, oq);
}

// ---------------------------------------------------------------------------
// fuse: fp16 hidden + logits GEMMs; parallelized softmax/tanh tail.
// ---------------------------------------------------------------------------
__global__ __launch_bounds__(256)
void fuse_kernel(const float* __restrict__ dkb1, const float* __restrict__ dkb2,
                 const float* __restrict__ gkb1, const float* __restrict__ gkb2,
                 const float* __restrict__ aff) {
    __shared__ u32t   s_x[8][64][8];
    __shared__ __half s_h[64][72];
    __shared__ float  s_l[2][9][64];
    __shared__ float  s_e[2][9][64];
    __shared__ float  s_is[2][64];
    __shared__ float  s_f[9][64];

    const int b    = blockIdx.y;
    const int px0  = blockIdx.x * 64;
    const int t    = threadIdx.x;
    const int warp = t >> 5, lane = t & 31;
    const int G    = lane >> 2, tig = lane & 3;
    const int mt   = warp & 3, nh = warp >> 2;
    const int c0   = mt * 16;

    {
        const u32t smb = (u32t)__cvta_generic_to_shared(&s_x[0][0][0]);
        for (int u = t; u < 1024; u += 256) {
            int ch = u >> 7, rem = u & 127;
            int px = rem >> 1, hf = rem & 1;
            const u32t* src = gt_in0 + (((size_t)b * 8 + ch) * HW2_ + px0 + px) * 8 + hf * 4;
            asm volatile("cp.async.cg.shared.global [%0], [%1], 16, 16;"
                         :: "r"(smb + (u32t)(((ch * 64 + px) * 8 + hf * 4) * 4)), "l"(src));
        }
        asm volatile("cp.async.commit_group;");
        asm volatile("cp.async.wait_group 0;");
    }
    __syncthreads();

#pragma unroll
    for (int branch = 0; branch < 2; branch++) {
        const float* B1v = branch ? gkb1 : dkb1;
        const float* B2v = branch ? gkb2 : dkb2;
        const u32t* w1 = gt_fw1 + branch * 2048;
        const u32t* w2 = gt_fw2 + branch * 512;

        if (branch) __syncthreads();

        float d[4][4];
#pragma unroll
        for (int nc = 0; nc < 4; nc++)
#pragma unroll
            for (int i = 0; i < 4; i++) d[nc][i] = 0.f;
#pragma unroll
        for (int kc = 0; kc < 4; kc++) {
            uint2 q0 = *(const uint2*)&w1[((kc * 64) + c0 + G)     * 8 + 2 * tig];
            uint2 q1 = *(const uint2*)&w1[((kc * 64) + c0 + G + 8) * 8 + 2 * tig];
#pragma unroll
            for (int nc = 0; nc < 4; nc++) {
                int px = nh * 32 + nc * 8 + G;
                uint2 bb = *(const uint2*)&s_x[branch * 4 + kc][px][2 * tig];
                mma_f16(d[nc], q0.x, q1.x, q0.y, q1.y, bb.x, bb.y);
            }
        }
        float bv0 = __ldg(&B1v[c0 + G]);
        float bv8 = __ldg(&B1v[c0 + G + 8]);
#pragma unroll
        for (int nc = 0; nc < 4; nc++) {
            int px = nh * 32 + nc * 8 + 2 * tig;
            s_h[px][c0 + G]         = __float2half_rn(fmaxf(d[nc][0] + bv0, 0.f));
            s_h[px + 1][c0 + G]     = __float2half_rn(fmaxf(d[nc][1] + bv0, 0.f));
            s_h[px][c0 + G + 8]     = __float2half_rn(fmaxf(d[nc][2] + bv8, 0.f));
            s_h[px + 1][c0 + G + 8] = __float2half_rn(fmaxf(d[nc][3] + bv8, 0.f));
        }
        __syncthreads();

        {
            const int n0 = warp * 8;
            float d2[4] = {0.f, 0.f, 0.f, 0.f};
#pragma unroll
            for (int kc = 0; kc < 4; kc++) {
                uint2 q0 = *(const uint2*)&w2[((kc * 16) + G)     * 8 + 2 * tig];
                uint2 q1 = *(const uint2*)&w2[((kc * 16) + G + 8) * 8 + 2 * tig];
                u32t b0 = *(const u32t*)&s_h[n0 + G][kc * 16 + 2 * tig];
                u32t b1 = *(const u32t*)&s_h[n0 + G][kc * 16 + 2 * tig + 8];
                mma_f16(d2, q0.x, q1.x, q0.y, q1.y, b0, b1);
            }
            float bj = __ldg(&B2v[G]);
            s_l[branch][G][n0 + 2 * tig]     = d2[0] + bj;
            s_l[branch][G][n0 + 2 * tig + 1] = d2[1] + bj;
            if (G == 0) {
                float b8 = __ldg(&B2v[8]);
                s_l[branch][8][n0 + 2 * tig]     = d2[2] + b8;
                s_l[branch][8][n0 + 2 * tig + 1] = d2[3] + b8;
            }
        }
    }
    __syncthreads();

    // phase A: per-(branch,px) softmax exps on 128 threads
    if (t < 128) {
        int br = t >> 6, px = t & 63;
        float mx = -1e30f;
#pragma unroll
        for (int j = 0; j < 9; j++) mx = fmaxf(mx, s_l[br][j][px]);
        float s = 0.f;
#pragma unroll
        for (int j = 0; j < 9; j++) {
            float e = expf(s_l[br][j][px] - mx);
            s_e[br][j][px] = e;
            s += e;
        }
        s_is[br][px] = 1.f / s;
    }
    __syncthreads();

    // phase B: fuse-combine + tanh over all 256 threads (576 items)
    {
        float affv = __ldg(&aff[0]) + 1e-8f;
        for (int idx = t; idx < 576; idx += 256) {
            int j = idx >> 6, px = idx & 63;
            float wm = g_wmap[(size_t)b * HW2_ + px0 + px];
            float fv = wm * (s_e[0][j][px] * s_is[0][px])
                     + (1.f - wm) * (s_e[1][j][px] * s_is[1][px]);
            s_f[j][px] = tanhf(fv) / affv;
        }
    }
    __syncthreads();

    // phase C: L1 normalize + write
    if (t < 64) {
        float asum = 0.f;
#pragma unroll
        for (int j = 0; j < 9; j++) asum += fabsf(s_f[j][t]);
        float inv_ks = 1.f / fmaxf(asum + 1e-4f, 1.0f);
#pragma unroll
        for (int j = 0; j < 9; j++)
            g_fuse[((size_t)b * 9 + j) * HW2_ + px0 + t] = s_f[j][t] * inv_ks;
    }
}

// ---------------------------------------------------------------------------
// gather with fused bilinear upsample — 16 channels per round (4 rounds)
// ---------------------------------------------------------------------------
__global__ __launch_bounds__(256)
void gather_kernel(float* __restrict__ out) {
    __shared__ float s_r3[16][8][21];
    __shared__ float s_up[16][12][37];
    const int b   = blockIdx.z;
    const int gx0 = blockIdx.x * 32;
    const int gy0 = blockIdx.y * 8;
    const int t   = threadIdx.x;
    const int xl  = t & 31, yl = t >> 5;
    const int gx  = gx0 + xl, gy = gy0 + yl;
    const int ly0 = gy0 / 2 - 2, lx0 = gx0 / 2 - 2;

    float f[9];
#pragma unroll
    for (int j = 0; j < 9; j++)
        f[j] = g_fuse[((size_t)b * 9 + j) * HW2_ + gy * W2_ + gx];

    for (int c0 = 0; c0 < 64; c0 += 16) {
        __syncthreads();
        for (int idx = t; idx < 2560; idx += 256) {
            int cl = idx / 160, rem = idx - cl * 160;
            int r = rem / 20, cc = rem - r * 20;
            int yy = min(max(ly0 + r, 0), 127);
            int xx = min(max(lx0 + cc, 0), 127);
            s_r3[cl][r][cc] = g_r3[((size_t)b * 64 + c0 + cl) * HW1_ + yy * 128 + xx];
        }
        __syncthreads();
        for (int idx = t; idx < 432; idx += 256) {
            int r = idx / 36, cc = idx - r * 36;
            int Y = gy0 + r - 2, X = gx0 + cc - 2;
            bool ok = (Y >= 0) && (Y < H2_) && (X >= 0) && (X < W2_);
            int m = Y >> 1, ya, yb; float wya, wyb;
            if (Y & 1) { ya = m; yb = min(m + 1, 127); wya = 0.75f; wyb = 0.25f; }
            else       { ya = max(m - 1, 0); yb = m;   wya = 0.25f; wyb = 0.75f; }
            int n = X >> 1, xa, xb; float wxa, wxb;
            if (X & 1) { xa = n; xb = min(n + 1, 127); wxa = 0.75f; wxb = 0.25f; }
            else       { xa = max(n - 1, 0); xb = n;   wxa = 0.25f; wxb = 0.75f; }
            int iya = min(max(ya - ly0, 0), 7), iyb = min(max(yb - ly0, 0), 7);
            int ixa = min(max(xa - lx0, 0), 20), ixb = min(max(xb - lx0, 0), 20);
            float waa = wya * wxa, wab = wya * wxb, wba = wyb * wxa, wbb = wyb * wxb;
#pragma unroll
            for (int cl = 0; cl < 16; cl++) {
                float v = waa * s_r3[cl][iya][ixa] + wab * s_r3[cl][iya][ixb]
                        + wba * s_r3[cl][iyb][ixa] + wbb * s_r3[cl][iyb][ixb];
                s_up[cl][r][cc] = ok ? v : 0.f;
            }
        }
        __syncthreads();
#pragma unroll
        for (int cl = 0; cl < 16; cl++) {
            float acc = 0.f;
#pragma unroll
            for (int ky = 0; ky < 3; ky++)
#pragma unroll
                for (int kx = 0; kx < 3; kx++)
                    acc += f[ky * 3 + kx] * s_up[cl][yl + 2 * ky][xl + 2 * kx];
            out[(((size_t)b * 64 + c0 + cl) * H2_ + gy) * W2_ + gx] = acc;
        }
    }
}

// ---------------------------------------------------------------------------
extern "C" void kernel_launch(void* const* d_in, const int* in_sizes, int n_in,
                              void* d_out, int out_size) {
    const float* depth  = (const float*)d_in[0];
    const float* guide  = (const float*)d_in[1];
    const float* inputs = (const float*)d_in[2];
    const float* dk_w1  = (const float*)d_in[3];
    const float* dk_b1  = (const float*)d_in[4];
    const float* dk_w2  = (const float*)d_in[5];
    const float* dk_b2  = (const float*)d_in[6];
    const float* gk_w1  = (const float*)d_in[7];
    const float* gk_b1  = (const float*)d_in[8];
    const float* gk_w2  = (const float*)d_in[9];
    const float* gk_b2  = (const float*)d_in[10];
    const float* wn_w1  = (const float*)d_in[11];
    const float* wn_b1  = (const float*)d_in[12];
    const float* wn_w2  = (const float*)d_in[13];
    const float* wn_b2  = (const float*)d_in[14];
    const float* wn_w3  = (const float*)d_in[15];
    const float* wn_b3  = (const float*)d_in[16];
    const float* rb_w   = (const float*)d_in[17];
    const float* rb_b   = (const float*)d_in[18];
    const float* aff    = (const float*)d_in[19];
    float* out = (float*)d_out;

    cudaFuncSetAttribute(k_stage1, cudaFuncAttributeMaxDynamicSharedMemorySize, SMEM_N4);
    cudaFuncSetAttribute(k_stage2, cudaFuncAttributeMaxDynamicSharedMemorySize, SMEM_N4);
    cudaFuncSetAttribute(k_stage3, cudaFuncAttributeMaxDynamicSharedMemorySize, SMEM_N2);
    cudaFuncSetAttribute(k_r4,     cudaFuncAttributeMaxDynamicSharedMemorySize, SMEM_N2);

    // prep (inputs + all weights in one launch)
    k_prep<<<(NPI_ + 136448 + 255) / 256, 256>>>(depth, guide, inputs,
                                                 wn_w1, wn_w2, rb_w, wn_w3,
                                                 dk_w1, gk_w1, dk_w2, gk_w2);

    // hybrid: stage1/2 oc-halves (3 blk/SM); stage3/r4 oc-quarters (4 blk/SM)
    k_stage1<<<1280, 256, SMEM_N4>>>(wn_b1, rb_b);
    k_stage2<<<1280, 256, SMEM_N4>>>(wn_b2, rb_b, inputs);
    k_stage3<<<1024, 256, SMEM_N2>>>(wn_b3, rb_b);

    // fuse then final residual conv
    dim3 gfuse(HW2_ / 64, B_);
    fuse_kernel<<<gfuse, 256>>>(dk_b1, dk_b2, gk_b1, gk_b2, aff);
    k_r4<<<512, 256, SMEM_N2>>>(rb_b);

    // fused upsample + gather
    dim3 ghi8(W2_ / 32, H2_ / 8, B_);
    gather_kernel<<<ghi8, 256>>>(out);
}